// round 5
// baseline (speedup 1.0000x reference)
#include <cuda_runtime.h>
#include <cuda_bf16.h>
#include <math.h>

// ---------------------------------------------------------------------------
// AttentionBasedPooling
//   h = tanh(x @ W1 + b1); z = h @ W2 + b2           (per-token logit)
//   segment softmax over sorted segment_ids (S segments)
//   context[s] = sum_n w[n] * x[n];  outputs: context [S,256] ++ weights [N]
// ---------------------------------------------------------------------------

#define D_DIM   256
#define H_DIM   128
#define MAXN    524288
#define MAXS    4096

typedef unsigned long long ull;

// scratch (allocation-free: __device__ globals)
__device__ float        g_z[MAXN];          // logits, then reused as e = exp(z - max)
__device__ unsigned int g_maxkey[MAXS];     // order-preserving encoded per-segment max
__device__ float        g_sum[MAXS];        // per-segment sum of exp
__device__ int          g_off[MAXS + 1];    // segment start offsets

// ---- packed f32x2 helpers (Blackwell full-rate fp32 path) ------------------
__device__ __forceinline__ ull ffma2(ull a, ull b, ull c) {
    ull d;
    asm("fma.rn.f32x2 %0, %1, %2, %3;" : "=l"(d) : "l"(a), "l"(b), "l"(c));
    return d;
}
__device__ __forceinline__ ull dup2(float v) {
    ull r;
    asm("mov.b64 %0, {%1, %1};" : "=l"(r) : "f"(v));
    return r;
}
__device__ __forceinline__ float2 unpk2(ull v) {
    float2 f;
    asm("mov.b64 {%0, %1}, %2;" : "=f"(f.x), "=f"(f.y) : "l"(v));
    return f;
}

// ---- order-preserving float <-> uint key for atomicMax ---------------------
__device__ __forceinline__ unsigned int enc_key(float f) {
    unsigned int u = __float_as_uint(f);
    return (u & 0x80000000u) ? ~u : (u | 0x80000000u);
}
__device__ __forceinline__ float dec_key(unsigned int u) {
    return (u & 0x80000000u) ? __uint_as_float(u & 0x7FFFFFFFu)
                             : __uint_as_float(~u);
}

// ---------------------------------------------------------------------------
// init: zero per-segment accumulators
// ---------------------------------------------------------------------------
__global__ void init_kernel(int S) {
    int i = blockIdx.x * blockDim.x + threadIdx.x;
    if (i < S) {
        g_maxkey[i] = 0u;   // decodes below every real key
        g_sum[i]    = 0.0f;
    }
}

// ---------------------------------------------------------------------------
// MLP logit GEMM: z[n] = tanh(x[n] @ W1 + b1) @ W2 + b2
// BM=128 tokens per block, full hidden (128), BK=32.
// 256 threads, each owns an 8x8 micro-tile; rows packed in f32x2 pairs.
// ---------------------------------------------------------------------------
#define BM 128
#define BK 32
#define XPAD 4   // pad Xs rows to reduce transpose-store bank conflicts

__global__ __launch_bounds__(256)
void logit_gemm_kernel(const float* __restrict__ x,
                       const float* __restrict__ W1,
                       const float* __restrict__ b1,
                       const float* __restrict__ W2,
                       const float* __restrict__ b2,
                       int N) {
    __shared__ float Xs[BK][BM + XPAD];   // [k][m], transposed tile
    __shared__ float Ws[BK][H_DIM];       // [k][h]
    __shared__ float sb1[H_DIM];
    __shared__ float sW2[H_DIM];

    const int tid = threadIdx.x;
    const int tx  = tid & 15;    // hidden-dim group (8 cols each)
    const int ty  = tid >> 4;    // token-row group (8 rows each)
    const int bm  = blockIdx.x * BM;

    if (tid < H_DIM) { sb1[tid] = b1[tid]; sW2[tid] = W2[tid]; }

    ull acc[4][8];
#pragma unroll
    for (int i = 0; i < 4; i++)
#pragma unroll
        for (int j = 0; j < 8; j++) acc[i][j] = 0ull;

    for (int kt = 0; kt < D_DIM; kt += BK) {
        // --- load X tile (128 x 32) transposed into Xs ---
#pragma unroll
        for (int it = 0; it < 4; it++) {
            int idx = tid + 256 * it;          // 1024 float4 total
            int row = idx >> 3;                // 8 float4 per row
            int c4  = idx & 7;
            float4 v = make_float4(0.f, 0.f, 0.f, 0.f);
            int grow = bm + row;
            if (grow < N)
                v = *reinterpret_cast<const float4*>(
                        x + (size_t)grow * D_DIM + kt + c4 * 4);
            Xs[c4 * 4 + 0][row] = v.x;
            Xs[c4 * 4 + 1][row] = v.y;
            Xs[c4 * 4 + 2][row] = v.z;
            Xs[c4 * 4 + 3][row] = v.w;

            // --- load W1 tile (32 x 128), direct copy ---
            int wrow = idx >> 5;               // 32 float4 per row
            int wc4  = idx & 31;
            *reinterpret_cast<float4*>(&Ws[wrow][wc4 * 4]) =
                *reinterpret_cast<const float4*>(
                    W1 + (size_t)(kt + wrow) * H_DIM + wc4 * 4);
        }
        __syncthreads();

#pragma unroll
        for (int k = 0; k < BK; k++) {
            const ull* xp = reinterpret_cast<const ull*>(&Xs[k][ty * 8]);
            ull a0 = xp[0], a1 = xp[1], a2 = xp[2], a3 = xp[3];
            const float4* wp = reinterpret_cast<const float4*>(&Ws[k][tx * 8]);
            float4 wA = wp[0], wB = wp[1];
            float wv[8] = {wA.x, wA.y, wA.z, wA.w, wB.x, wB.y, wB.z, wB.w};
#pragma unroll
            for (int j = 0; j < 8; j++) {
                ull bj = dup2(wv[j]);
                acc[0][j] = ffma2(a0, bj, acc[0][j]);
                acc[1][j] = ffma2(a1, bj, acc[1][j]);
                acc[2][j] = ffma2(a2, bj, acc[2][j]);
                acc[3][j] = ffma2(a3, bj, acc[3][j]);
            }
        }
        __syncthreads();
    }

    // --- epilogue: tanh, dot with W2, reduce across the 16 tx groups ---
    float zp[8];
#pragma unroll
    for (int r = 0; r < 8; r++) zp[r] = 0.f;

#pragma unroll
    for (int j = 0; j < 8; j++) {
        int c = tx * 8 + j;
        float bb = sb1[c];
        float w2 = sW2[c];
#pragma unroll
        for (int i = 0; i < 4; i++) {
            float2 u = unpk2(acc[i][j]);
            zp[2 * i + 0] += tanhf(u.x + bb) * w2;
            zp[2 * i + 1] += tanhf(u.y + bb) * w2;
        }
    }

    // reuse Xs memory for the cross-tx reduction: red[128][17]
    float (*red)[17] = reinterpret_cast<float (*)[17]>(&Xs[0][0]);
#pragma unroll
    for (int i = 0; i < 8; i++) red[ty * 8 + i][tx] = zp[i];
    __syncthreads();

    if (tid < BM) {
        float s = b2[0];
#pragma unroll
        for (int k = 0; k < 16; k++) s += red[tid][k];
        int gr = bm + tid;
        if (gr < N) g_z[gr] = s;
    }
}

// ---------------------------------------------------------------------------
// per-segment max of z (run-aggregated atomics, ids are sorted)
// ---------------------------------------------------------------------------
#define ITEMS 8
__global__ void segmax_kernel(const int* __restrict__ seg, int N) {
    int base = (blockIdx.x * blockDim.x + threadIdx.x) * ITEMS;
    if (base >= N) return;
    int end = min(base + ITEMS, N);
    int cur = seg[base];
    float m = g_z[base];
    for (int n = base + 1; n < end; n++) {
        int s = seg[n];
        float v = g_z[n];
        if (s == cur) {
            m = fmaxf(m, v);
        } else {
            atomicMax(&g_maxkey[cur], enc_key(m));
            cur = s; m = v;
        }
    }
    atomicMax(&g_maxkey[cur], enc_key(m));
}

// ---------------------------------------------------------------------------
// e = exp(z - segmax); per-segment sum (run-aggregated atomics). g_z -> e.
// ---------------------------------------------------------------------------
__global__ void expsum_kernel(const int* __restrict__ seg, int N) {
    int base = (blockIdx.x * blockDim.x + threadIdx.x) * ITEMS;
    if (base >= N) return;
    int end = min(base + ITEMS, N);
    int cur = seg[base];
    float mx = dec_key(g_maxkey[cur]);
    float acc = 0.f;
    for (int n = base; n < end; n++) {
        int s = seg[n];
        if (s != cur) {
            atomicAdd(&g_sum[cur], acc);
            cur = s;
            mx = dec_key(g_maxkey[cur]);
            acc = 0.f;
        }
        float e = expf(g_z[n] - mx);
        g_z[n] = e;
        acc += e;
    }
    atomicAdd(&g_sum[cur], acc);
}

// ---------------------------------------------------------------------------
// segment offsets via binary search (handles empty segments for free)
// ---------------------------------------------------------------------------
__global__ void offsets_kernel(const int* __restrict__ seg, int N, int S) {
    int s = blockIdx.x * blockDim.x + threadIdx.x;
    if (s > S) return;
    int lo = 0, hi = N;
    while (lo < hi) {
        int mid = (lo + hi) >> 1;
        if (seg[mid] < s) lo = mid + 1; else hi = mid;
    }
    g_off[s] = lo;
}

// ---------------------------------------------------------------------------
// context vectors + attention-weight output. One block per segment.
// Thread d accumulates column d over the segment's tokens.
// ---------------------------------------------------------------------------
__global__ __launch_bounds__(256)
void context_kernel(const float* __restrict__ x,
                    float* __restrict__ ctx_out,
                    float* __restrict__ w_out) {
    int s = blockIdx.x;
    int d = threadIdx.x;
    int start = g_off[s];
    int end   = g_off[s + 1];
    float inv = (end > start) ? (1.0f / g_sum[s]) : 0.0f;

    // attention-weight output (coalesced)
    for (int n = start + d; n < end; n += 256)
        w_out[n] = g_z[n] * inv;

    float acc = 0.f;
    int n = start;
    for (; n + 4 <= end; n += 4) {
        float w0 = g_z[n + 0] * inv;
        float w1 = g_z[n + 1] * inv;
        float w2 = g_z[n + 2] * inv;
        float w3 = g_z[n + 3] * inv;
        acc += w0 * __ldg(x + (size_t)(n + 0) * D_DIM + d);
        acc += w1 * __ldg(x + (size_t)(n + 1) * D_DIM + d);
        acc += w2 * __ldg(x + (size_t)(n + 2) * D_DIM + d);
        acc += w3 * __ldg(x + (size_t)(n + 3) * D_DIM + d);
    }
    for (; n < end; n++)
        acc += g_z[n] * inv * __ldg(x + (size_t)n * D_DIM + d);

    ctx_out[(size_t)s * D_DIM + d] = acc;
}

// ---------------------------------------------------------------------------
// launch
// ---------------------------------------------------------------------------
extern "C" void kernel_launch(void* const* d_in, const int* in_sizes, int n_in,
                              void* d_out, int out_size) {
    const float* x   = (const float*)d_in[0];
    const int*   seg = (const int*)d_in[1];

    // locate MLP params by size (robust to optional num_segments scalar input)
    int wi = 2;
    for (int i = 2; i < n_in; i++) {
        if (in_sizes[i] == D_DIM * H_DIM) { wi = i; break; }
    }
    const float* W1 = (const float*)d_in[wi + 0];
    const float* b1 = (const float*)d_in[wi + 1];
    const float* W2 = (const float*)d_in[wi + 2];
    const float* b2 = (const float*)d_in[wi + 3];

    int N = in_sizes[1];
    long long rem = (long long)out_size - (long long)N;
    int S = (rem > 0 && rem % D_DIM == 0) ? (int)(rem / D_DIM)
                                          : (out_size / D_DIM);
    if (S > MAXS) S = MAXS;

    float* ctx_out = (float*)d_out;                        // [S, 256]
    float* w_out   = (float*)d_out + (size_t)S * D_DIM;    // [N]

    init_kernel<<<(S + 255) / 256, 256>>>(S);
    logit_gemm_kernel<<<(N + BM - 1) / BM, 256>>>(x, W1, b1, W2, b2, N);

    int rblocks = (N + 256 * ITEMS - 1) / (256 * ITEMS);
    segmax_kernel<<<rblocks, 256>>>(seg, N);
    expsum_kernel<<<rblocks, 256>>>(seg, N);
    offsets_kernel<<<(S + 1 + 255) / 256, 256>>>(seg, N, S);
    context_kernel<<<S, 256>>>(x, ctx_out, w_out);
}

// round 8
// speedup vs baseline: 1.9898x; 1.9898x over previous
#include <cuda_runtime.h>
#include <cuda_bf16.h>
#include <math.h>
#include <stdint.h>

// ---------------------------------------------------------------------------
// AttentionBasedPooling — round 7: warp-level mma.sync (portable PTX) GEMM
//   h = tanh(x @ W1 + b1); z = h @ W2 + b2
//   segment softmax over sorted segment_ids; context[s] = sum w[n] x[n]
// NOTE: tcgen05/TMEM is 'a'-suffix gated and the harness ptxas pass targets
// family-portable sm_103 — so tensor work goes through ldmatrix + mma.sync,
// which ARE portable (sm_80+). bf16 hi/lo split keeps fp32-grade accuracy.
// ---------------------------------------------------------------------------

#define D_DIM   256
#define H_DIM   128
#define MAXN    524288
#define MAXS    4096

__device__ float        g_z[MAXN];
__device__ unsigned int g_maxkey[MAXS];
__device__ float        g_sum[MAXS];
__device__ int          g_off[MAXS + 1];

// ---------------------------------------------------------------------------
// helpers
// ---------------------------------------------------------------------------
__device__ __forceinline__ uint32_t smem_u32(const void* p) {
    uint32_t a;
    asm("{ .reg .u64 t; cvta.to.shared.u64 t, %1; cvt.u32.u64 %0, t; }"
        : "=r"(a) : "l"(p));
    return a;
}

#define LDM_X4(r0, r1, r2, r3, addr) \
    asm volatile("ldmatrix.sync.aligned.m8n8.x4.shared.b16 {%0,%1,%2,%3}, [%4];" \
                 : "=r"(r0), "=r"(r1), "=r"(r2), "=r"(r3) : "r"(addr))

__device__ __forceinline__ void mma_bf16(float* c, const uint32_t* a,
                                         const uint32_t* b) {
    asm volatile(
        "mma.sync.aligned.m16n8k16.row.col.f32.bf16.bf16.f32 "
        "{%0,%1,%2,%3}, {%4,%5,%6,%7}, {%8,%9}, {%0,%1,%2,%3};"
        : "+f"(c[0]), "+f"(c[1]), "+f"(c[2]), "+f"(c[3])
        : "r"(a[0]), "r"(a[1]), "r"(a[2]), "r"(a[3]), "r"(b[0]), "r"(b[1]));
}

__device__ __forceinline__ unsigned int enc_key(float f) {
    unsigned int u = __float_as_uint(f);
    return (u & 0x80000000u) ? ~u : (u | 0x80000000u);
}
__device__ __forceinline__ float dec_key(unsigned int u) {
    return (u & 0x80000000u) ? __uint_as_float(u & 0x7FFFFFFFu)
                             : __uint_as_float(~u);
}

// ---------------------------------------------------------------------------
// init
// ---------------------------------------------------------------------------
__global__ void init_kernel(int S) {
    int i = blockIdx.x * blockDim.x + threadIdx.x;
    if (i < S) {
        g_maxkey[i] = 0u;
        g_sum[i]    = 0.0f;
    }
}

// ---------------------------------------------------------------------------
// logit GEMM via mma.sync: z[n] = tanh(x[n] @ W1 + b1) @ W2 + b2
// BM=128 tokens/CTA, N=128 hidden, K=256 in 4 chunks of 64.
// bf16 hi/lo split; acc += Ah*Bh + Ah*Bl + Al*Bh in fp32.
// ---------------------------------------------------------------------------
#define KC        64
#define PITCHB    144                  // bytes per smem row (64 bf16 + 8 pad)
#define TILE_B    (128 * PITCHB)       // 18432 bytes per tile side
#define SA_HI     0
#define SA_LO     (TILE_B)
#define SB_HI     (2 * TILE_B)
#define SB_LO     (3 * TILE_B)
#define SMEM_TILES (4 * TILE_B)        // 73728 bytes dynamic

__global__ __launch_bounds__(256, 2)
void logit_mma_kernel(const float* __restrict__ x,
                      const float* __restrict__ W1,
                      const float* __restrict__ b1,
                      const float* __restrict__ W2,
                      const float* __restrict__ b2,
                      int N) {
    extern __shared__ char smem[];
    __shared__ float sb1[H_DIM];
    __shared__ float sW2[H_DIM];
    __shared__ float zred[128][5];
    __shared__ float sb2s;

    const uint32_t sbase = smem_u32(smem);
    const int tid = threadIdx.x;
    const int wid = tid >> 5;
    const int l   = tid & 31;
    const int bm  = blockIdx.x * 128;
    const int warpM = (wid & 1) * 64;     // token rows of this warp
    const int warpN = (wid >> 1) * 32;    // hidden cols of this warp

    if (tid < H_DIM) { sb1[tid] = b1[tid]; sW2[tid] = W2[tid]; }
    if (tid == 0) sb2s = b2[0];

    float acc[4][4][4];
#pragma unroll
    for (int mt = 0; mt < 4; mt++)
#pragma unroll
        for (int nt = 0; nt < 4; nt++)
#pragma unroll
            for (int r = 0; r < 4; r++) acc[mt][nt][r] = 0.f;

    // lane-dependent ldmatrix base offsets (bytes)
    const int g  = l >> 3;
    const int lr = l & 7;
    const uint32_t a_base =
        (uint32_t)((warpM + (g & 1) * 8 + lr) * PITCHB + ((g >> 1) * 8) * 2);
    const uint32_t b_base =
        (uint32_t)((warpN + (g >> 1) * 8 + lr) * PITCHB + ((g & 1) * 8) * 2);

    for (int chunk = 0; chunk < 4; chunk++) {
        const int kt = chunk * KC;

        // --- A tile: x[bm..bm+127][kt..kt+63] -> bf16 hi/lo ---
#pragma unroll
        for (int it = 0; it < 8; it++) {
            int idx = tid + 256 * it;          // 2048 float4 slots
            int row = idx >> 4;                // 16 float4 per row
            int k0  = (idx & 15) << 2;
            float4 v = make_float4(0.f, 0.f, 0.f, 0.f);
            int gr = bm + row;
            if (gr < N)
                v = *reinterpret_cast<const float4*>(
                        x + (size_t)gr * D_DIM + kt + k0);
            float vv[4] = {v.x, v.y, v.z, v.w};
            __nv_bfloat16 h[4], lo[4];
#pragma unroll
            for (int j = 0; j < 4; j++) {
                h[j]  = __float2bfloat16_rn(vv[j]);
                lo[j] = __float2bfloat16_rn(vv[j] - __bfloat162float(h[j]));
            }
            char* ph = smem + SA_HI + row * PITCHB + k0 * 2;
            char* pl = smem + SA_LO + row * PITCHB + k0 * 2;
            __nv_bfloat162 t;
            t.x = h[0];  t.y = h[1];  *(__nv_bfloat162*)(ph    ) = t;
            t.x = h[2];  t.y = h[3];  *(__nv_bfloat162*)(ph + 4) = t;
            t.x = lo[0]; t.y = lo[1]; *(__nv_bfloat162*)(pl    ) = t;
            t.x = lo[2]; t.y = lo[3]; *(__nv_bfloat162*)(pl + 4) = t;
        }

        // --- B tile: Bs[n][k] = W1[kt+k][n] -> bf16 hi/lo (transposed read) ---
        {
            int n  = tid & 127;
            int kh = (tid >> 7) * 32;
#pragma unroll
            for (int kk = 0; kk < 32; kk += 2) {
                int k = kh + kk;
                float w0 = W1[(size_t)(kt + k) * H_DIM + n];
                float w1 = W1[(size_t)(kt + k + 1) * H_DIM + n];
                __nv_bfloat16 h0 = __float2bfloat16_rn(w0);
                __nv_bfloat16 h1 = __float2bfloat16_rn(w1);
                __nv_bfloat16 l0 = __float2bfloat16_rn(w0 - __bfloat162float(h0));
                __nv_bfloat16 l1 = __float2bfloat16_rn(w1 - __bfloat162float(h1));
                char* ph = smem + SB_HI + n * PITCHB + k * 2;
                char* pl = smem + SB_LO + n * PITCHB + k * 2;
                __nv_bfloat162 t;
                t.x = h0; t.y = h1; *(__nv_bfloat162*)ph = t;
                t.x = l0; t.y = l1; *(__nv_bfloat162*)pl = t;
            }
        }
        __syncthreads();

        // --- 4 k-steps of 16 ---
#pragma unroll
        for (int ks = 0; ks < 4; ks++) {
            const uint32_t ko = ks * 32;       // 16 bf16 = 32 bytes

            uint32_t Af[4][4];                 // A frags (hi, then reused for lo)
            uint32_t Bh[4][2], Bl[4][2];

#pragma unroll
            for (int mt = 0; mt < 4; mt++) {
                uint32_t addr = sbase + SA_HI + a_base + ko + mt * (16 * PITCHB);
                LDM_X4(Af[mt][0], Af[mt][1], Af[mt][2], Af[mt][3], addr);
            }
#pragma unroll
            for (int p = 0; p < 2; p++) {
                uint32_t addr = sbase + SB_HI + b_base + ko + p * (16 * PITCHB);
                LDM_X4(Bh[2*p][0], Bh[2*p][1], Bh[2*p+1][0], Bh[2*p+1][1], addr);
                addr = sbase + SB_LO + b_base + ko + p * (16 * PITCHB);
                LDM_X4(Bl[2*p][0], Bl[2*p][1], Bl[2*p+1][0], Bl[2*p+1][1], addr);
            }

#pragma unroll
            for (int mt = 0; mt < 4; mt++)
#pragma unroll
                for (int nt = 0; nt < 4; nt++)
                    mma_bf16(acc[mt][nt], Af[mt], Bh[nt]);
#pragma unroll
            for (int mt = 0; mt < 4; mt++)
#pragma unroll
                for (int nt = 0; nt < 4; nt++)
                    mma_bf16(acc[mt][nt], Af[mt], Bl[nt]);

            // reuse Af for A-lo frags
#pragma unroll
            for (int mt = 0; mt < 4; mt++) {
                uint32_t addr = sbase + SA_LO + a_base + ko + mt * (16 * PITCHB);
                LDM_X4(Af[mt][0], Af[mt][1], Af[mt][2], Af[mt][3], addr);
            }
#pragma unroll
            for (int mt = 0; mt < 4; mt++)
#pragma unroll
                for (int nt = 0; nt < 4; nt++)
                    mma_bf16(acc[mt][nt], Af[mt], Bh[nt]);
        }
        __syncthreads();
    }

    // --- epilogue: tanh + dot(W2), reduce cols ---
    float zp[4][2];
#pragma unroll
    for (int mt = 0; mt < 4; mt++) { zp[mt][0] = 0.f; zp[mt][1] = 0.f; }

#pragma unroll
    for (int mt = 0; mt < 4; mt++) {
#pragma unroll
        for (int nt = 0; nt < 4; nt++) {
            int c0 = warpN + nt * 8 + 2 * (l & 3);
            float bb0 = sb1[c0],     w0 = sW2[c0];
            float bb1 = sb1[c0 + 1], w1 = sW2[c0 + 1];
            zp[mt][0] += tanhf(acc[mt][nt][0] + bb0) * w0
                       + tanhf(acc[mt][nt][1] + bb1) * w1;
            zp[mt][1] += tanhf(acc[mt][nt][2] + bb0) * w0
                       + tanhf(acc[mt][nt][3] + bb1) * w1;
        }
        // reduce over the 4 lanes sharing a row (l&3)
#pragma unroll
        for (int i = 0; i < 2; i++) {
            zp[mt][i] += __shfl_xor_sync(0xFFFFFFFFu, zp[mt][i], 1);
            zp[mt][i] += __shfl_xor_sync(0xFFFFFFFFu, zp[mt][i], 2);
        }
    }
    if ((l & 3) == 0) {
        int ng = wid >> 1;
#pragma unroll
        for (int mt = 0; mt < 4; mt++) {
            int r0 = warpM + mt * 16 + (l >> 2);
            zred[r0][ng]     = zp[mt][0];
            zred[r0 + 8][ng] = zp[mt][1];
        }
    }
    __syncthreads();
    if (tid < 128) {
        float z = zred[tid][0] + zred[tid][1] + zred[tid][2] + zred[tid][3] + sb2s;
        int gr = bm + tid;
        if (gr < N) g_z[gr] = z;
    }
}

// ---------------------------------------------------------------------------
// per-segment max of z (run-aggregated atomics, ids sorted)
// ---------------------------------------------------------------------------
#define ITEMS 8
__global__ void segmax_kernel(const int* __restrict__ seg, int N) {
    int base = (blockIdx.x * blockDim.x + threadIdx.x) * ITEMS;
    if (base >= N) return;
    int end = min(base + ITEMS, N);
    int cur = seg[base];
    float m = g_z[base];
    for (int n = base + 1; n < end; n++) {
        int s = seg[n];
        float v = g_z[n];
        if (s == cur) {
            m = fmaxf(m, v);
        } else {
            atomicMax(&g_maxkey[cur], enc_key(m));
            cur = s; m = v;
        }
    }
    atomicMax(&g_maxkey[cur], enc_key(m));
}

// ---------------------------------------------------------------------------
// e = exp(z - segmax); per-segment sum. g_z -> e.
// ---------------------------------------------------------------------------
__global__ void expsum_kernel(const int* __restrict__ seg, int N) {
    int base = (blockIdx.x * blockDim.x + threadIdx.x) * ITEMS;
    if (base >= N) return;
    int end = min(base + ITEMS, N);
    int cur = seg[base];
    float mx = dec_key(g_maxkey[cur]);
    float acc = 0.f;
    for (int n = base; n < end; n++) {
        int s = seg[n];
        if (s != cur) {
            atomicAdd(&g_sum[cur], acc);
            cur = s;
            mx = dec_key(g_maxkey[cur]);
            acc = 0.f;
        }
        float e = expf(g_z[n] - mx);
        g_z[n] = e;
        acc += e;
    }
    atomicAdd(&g_sum[cur], acc);
}

// ---------------------------------------------------------------------------
// segment offsets via binary search
// ---------------------------------------------------------------------------
__global__ void offsets_kernel(const int* __restrict__ seg, int N, int S) {
    int s = blockIdx.x * blockDim.x + threadIdx.x;
    if (s > S) return;
    int lo = 0, hi = N;
    while (lo < hi) {
        int mid = (lo + hi) >> 1;
        if (seg[mid] < s) lo = mid + 1; else hi = mid;
    }
    g_off[s] = lo;
}

// ---------------------------------------------------------------------------
// context vectors + attention-weight output. One block per segment.
// ---------------------------------------------------------------------------
__global__ __launch_bounds__(256)
void context_kernel(const float* __restrict__ x,
                    float* __restrict__ ctx_out,
                    float* __restrict__ w_out) {
    int s = blockIdx.x;
    int d = threadIdx.x;
    int start = g_off[s];
    int end   = g_off[s + 1];
    float inv = (end > start) ? (1.0f / g_sum[s]) : 0.0f;

    for (int n = start + d; n < end; n += 256)
        w_out[n] = g_z[n] * inv;

    float acc = 0.f;
    int n = start;
    for (; n + 4 <= end; n += 4) {
        float w0 = g_z[n + 0] * inv;
        float w1 = g_z[n + 1] * inv;
        float w2 = g_z[n + 2] * inv;
        float w3 = g_z[n + 3] * inv;
        acc += w0 * __ldg(x + (size_t)(n + 0) * D_DIM + d);
        acc += w1 * __ldg(x + (size_t)(n + 1) * D_DIM + d);
        acc += w2 * __ldg(x + (size_t)(n + 2) * D_DIM + d);
        acc += w3 * __ldg(x + (size_t)(n + 3) * D_DIM + d);
    }
    for (; n < end; n++)
        acc += g_z[n] * inv * __ldg(x + (size_t)n * D_DIM + d);

    ctx_out[(size_t)s * D_DIM + d] = acc;
}

// ---------------------------------------------------------------------------
// launch
// ---------------------------------------------------------------------------
extern "C" void kernel_launch(void* const* d_in, const int* in_sizes, int n_in,
                              void* d_out, int out_size) {
    const float* x   = (const float*)d_in[0];
    const int*   seg = (const int*)d_in[1];

    int wi = 2;
    for (int i = 2; i < n_in; i++) {
        if (in_sizes[i] == D_DIM * H_DIM) { wi = i; break; }
    }
    const float* W1 = (const float*)d_in[wi + 0];
    const float* b1 = (const float*)d_in[wi + 1];
    const float* W2 = (const float*)d_in[wi + 2];
    const float* b2 = (const float*)d_in[wi + 3];

    int N = in_sizes[1];
    long long rem = (long long)out_size - (long long)N;
    int S = (rem > 0 && rem % D_DIM == 0) ? (int)(rem / D_DIM)
                                          : (out_size / D_DIM);
    if (S > MAXS) S = MAXS;

    float* ctx_out = (float*)d_out;
    float* w_out   = (float*)d_out + (size_t)S * D_DIM;

    cudaFuncSetAttribute(logit_mma_kernel,
                         cudaFuncAttributeMaxDynamicSharedMemorySize, SMEM_TILES);

    init_kernel<<<(S + 255) / 256, 256>>>(S);
    logit_mma_kernel<<<(N + 127) / 128, 256, SMEM_TILES>>>(x, W1, b1, W2, b2, N);

    int rblocks = (N + 256 * ITEMS - 1) / (256 * ITEMS);
    segmax_kernel<<<rblocks, 256>>>(seg, N);
    expsum_kernel<<<rblocks, 256>>>(seg, N);
    offsets_kernel<<<(S + 1 + 255) / 256, 256>>>(seg, N, S);
    context_kernel<<<S, 256>>>(x, ctx_out, w_out);
}